// round 1
// baseline (speedup 1.0000x reference)
#include <cuda_runtime.h>
#include <math.h>

// Shapes: feature (2,16,128,128,128) f32, net_output (2,3,128,128,128) f32,
// target (2,1,128,128,128) i32. Output: scalar f32.
#define VV   (128*128*128)      /* 2^21 voxels per batch */
#define NV   (2*VV)             /* 4,194,304 */
#define NV4  (NV/4)
#define NWORDS (NV/64)          /* 65536 bitset words */
#define TOPN 250
#define EQCAP 4096

// ---------------- device scratch (static allocation only) ----------------
// g_red layout: 0 ce_sum | 1..3 sum_p[c] | 4..6 tp[c] | 7..9 cnt[c]
//               10 pos_cos_sum | 11..26 featsum[16]
//               27 easy_sum | 28 easy_cnt | 29 fneg_sum | 30 fneg_cnt
__device__ double g_red[32];
__device__ float  g_stdn[16];
__device__ unsigned g_histA[2048];
__device__ unsigned g_histB[2048];
__device__ unsigned g_histC[1024];
__device__ unsigned g_p1, g_p2, g_p3, g_cgt, g_eqcnt;
__device__ int g_eq[EQCAP];
__device__ float g_cos[NV];
__device__ unsigned long long g_pos[NWORDS];
__device__ unsigned long long g_hi[NWORDS];
__device__ unsigned long long g_tmp1[NWORDS];
__device__ unsigned long long g_tmp2[NWORDS];
__device__ unsigned long long g_posdil[NWORDS];
__device__ unsigned long long g_hidil[NWORDS];

// ---------------- helpers ----------------
__device__ __forceinline__ unsigned fmono(float f) {
    unsigned u = __float_as_uint(f);
    return (u & 0x80000000u) ? ~u : (u | 0x80000000u);
}

__device__ __forceinline__ double warp_sum(double v) {
#pragma unroll
    for (int o = 16; o; o >>= 1) v += __shfl_down_sync(0xffffffffu, v, o);
    return v;
}

template<int N>
__device__ __forceinline__ void block_accumulate(const double* vals, int base) {
    __shared__ double sh[N];
    if (threadIdx.x < N) sh[threadIdx.x] = 0.0;
    __syncthreads();
    int lane = threadIdx.x & 31;
#pragma unroll
    for (int k = 0; k < N; k++) {
        double w = warp_sum(vals[k]);
        if (lane == 0 && w != 0.0) atomicAdd(&sh[k], w);
    }
    __syncthreads();
    if (threadIdx.x < N) atomicAdd(&g_red[base + threadIdx.x], sh[threadIdx.x]);
}

// ---------------- K0: zero scratch (fresh per graph replay) ----------------
__global__ void k_zero() {
    int i = blockIdx.x * blockDim.x + threadIdx.x;
    if (i < 2048) { g_histA[i] = 0; g_histB[i] = 0; }
    if (i < 1024) { g_histC[i] = 0; }
    if (i < NWORDS) { g_pos[i] = 0ull; g_hi[i] = 0ull; }
    if (i < 32) g_red[i] = 0.0;
    if (i == 0) { g_cgt = 0u; g_eqcnt = 0u; }
}

// ---------------- K1: CE + Dice statistics ----------------
__global__ void k_cedice(const float* __restrict__ net, const int* __restrict__ tgt) {
    double acc[10];
#pragma unroll
    for (int k = 0; k < 10; k++) acc[k] = 0.0;
    int nt = gridDim.x * blockDim.x;
    for (int g = blockIdx.x * blockDim.x + threadIdx.x; g < NV4; g += nt) {
        int i0 = g << 2;
        int b = i0 >> 21; int v = i0 & (VV - 1);
        const float* base = net + (size_t)b * 3 * VV + v;
        float4 x0 = *(const float4*)(base);
        float4 x1 = *(const float4*)(base + VV);
        float4 x2 = *(const float4*)(base + 2 * (size_t)VV);
        int4 tt = *(const int4*)(tgt + i0);
        float a0[4] = {x0.x, x0.y, x0.z, x0.w};
        float a1[4] = {x1.x, x1.y, x1.z, x1.w};
        float a2[4] = {x2.x, x2.y, x2.z, x2.w};
        int ts[4] = {tt.x, tt.y, tt.z, tt.w};
#pragma unroll
        for (int j = 0; j < 4; j++) {
            float xa = a0[j], xb = a1[j], xc = a2[j];
            float m = fmaxf(xa, fmaxf(xb, xc));
            float e0 = __expf(xa - m), e1 = __expf(xb - m), e2 = __expf(xc - m);
            float ssum = e0 + e1 + e2;
            float ls = __logf(ssum);
            int t = ts[j];
            float xt = (t == 0) ? xa : ((t == 1) ? xb : xc);
            acc[0] += (double)(xt - m - ls);
            float inv = 1.0f / ssum;
            float p0 = e0 * inv, p1 = e1 * inv, p2 = e2 * inv;
            acc[1] += p0; acc[2] += p1; acc[3] += p2;
            acc[4 + t] += (t == 0) ? p0 : ((t == 1) ? p1 : p2);
            acc[7 + t] += 1.0;
        }
    }
    block_accumulate<10>(acc, 0);
}

// ---------------- K2: per-channel feature sum over positives ----------------
__global__ void k_featsum(const float* __restrict__ feat, const int* __restrict__ tgt) {
    double s[16];
#pragma unroll
    for (int c = 0; c < 16; c++) s[c] = 0.0;
    int nt = gridDim.x * blockDim.x;
    for (int g = blockIdx.x * blockDim.x + threadIdx.x; g < NV4; g += nt) {
        int i0 = g << 2;
        int b = i0 >> 21; int v = i0 & (VV - 1);
        int4 tt = *(const int4*)(tgt + i0);
        float m0 = (tt.x == 1) ? 1.0f : 0.0f;
        float m1 = (tt.y == 1) ? 1.0f : 0.0f;
        float m2 = (tt.z == 1) ? 1.0f : 0.0f;
        float m3 = (tt.w == 1) ? 1.0f : 0.0f;
        const float* fb = feat + (size_t)b * 16 * VV + v;
#pragma unroll
        for (int c = 0; c < 16; c++) {
            float4 x = *(const float4*)(fb + (size_t)c * VV);
            s[c] += (double)(x.x * m0 + x.y * m1 + x.z * m2 + x.w * m3);
        }
    }
    block_accumulate<16>(s, 11);
}

// ---------------- K3: normalize the positive-mean feature ----------------
__global__ void k_stdn() {
    if (threadIdx.x == 0 && blockIdx.x == 0) {
        double cnt = g_red[8];                 // count of target==1
        double m[16]; double n2 = 0.0;
#pragma unroll
        for (int c = 0; c < 16; c++) {
            double mv = g_red[11 + c] / fmax(cnt, 1.0);
            mv = (cnt > 0.0) ? mv : 0.0;
            m[c] = mv; n2 += mv * mv;
        }
        double nrm = fmax(sqrt(n2), 1e-12);
#pragma unroll
        for (int c = 0; c < 16; c++) g_stdn[c] = (float)(m[c] / nrm);
    }
}

// ---------------- K4: cos map + pos bitset + pos cos sum + level-0 hist ----
__global__ void k_cos(const float* __restrict__ feat, const int* __restrict__ tgt) {
    __shared__ unsigned hh[2048];
    for (int i = threadIdx.x; i < 2048; i += blockDim.x) hh[i] = 0;
    __syncthreads();
    float sn[16];
#pragma unroll
    for (int c = 0; c < 16; c++) sn[c] = g_stdn[c];
    double psum = 0.0;
    int nt = gridDim.x * blockDim.x;
    for (int g = blockIdx.x * blockDim.x + threadIdx.x; g < NV4; g += nt) {
        int i0 = g << 2;
        int b = i0 >> 21; int v = i0 & (VV - 1);
        const float* fb = feat + (size_t)b * 16 * VV + v;
        float d0 = 0, d1 = 0, d2 = 0, d3 = 0;
        float n0 = 0, n1 = 0, n2 = 0, n3 = 0;
#pragma unroll
        for (int c = 0; c < 16; c++) {
            float4 x = *(const float4*)(fb + (size_t)c * VV);
            d0 += x.x * sn[c]; n0 += x.x * x.x;
            d1 += x.y * sn[c]; n1 += x.y * x.y;
            d2 += x.z * sn[c]; n2 += x.z * x.z;
            d3 += x.w * sn[c]; n3 += x.w * x.w;
        }
        float4 cs;
        cs.x = d0 / fmaxf(sqrtf(n0), 1e-12f);
        cs.y = d1 / fmaxf(sqrtf(n1), 1e-12f);
        cs.z = d2 / fmaxf(sqrtf(n2), 1e-12f);
        cs.w = d3 / fmaxf(sqrtf(n3), 1e-12f);
        *(float4*)(g_cos + i0) = cs;
        int4 tt = *(const int4*)(tgt + i0);
        float cj[4] = {cs.x, cs.y, cs.z, cs.w};
        int ts[4] = {tt.x, tt.y, tt.z, tt.w};
        unsigned posbits = 0;
#pragma unroll
        for (int j = 0; j < 4; j++) {
            if (ts[j] == 1) { psum += (double)cj[j]; posbits |= (1u << j); }
            else if (ts[j] == 0) { atomicAdd(&hh[fmono(cj[j]) >> 21], 1u); }
        }
        if (posbits)
            atomicOr(&g_pos[i0 >> 6], ((unsigned long long)posbits) << (i0 & 63));
    }
    __syncthreads();
    for (int i = threadIdx.x; i < 2048; i += blockDim.x) {
        unsigned hv = hh[i];
        if (hv) atomicAdd(&g_histA[i], hv);
    }
    double one[1] = {psum};
    block_accumulate<1>(one, 10);
}

// ---------------- radix-select one level (single block) ----------------
__global__ void k_select(int level) {
    __shared__ unsigned sh[2048];
    __shared__ unsigned csum[256];
    const unsigned* hist = (level == 0) ? g_histA : ((level == 1) ? g_histB : g_histC);
    int nbins = (level == 2) ? 1024 : 2048;
    int per = nbins / 256;
    for (int i = threadIdx.x; i < nbins; i += 256) sh[i] = hist[i];
    __syncthreads();
    unsigned s = 0;
    for (int j = 0; j < per; j++) s += sh[threadIdx.x * per + j];
    csum[threadIdx.x] = s;
    __syncthreads();
    if (threadIdx.x == 0) {
        unsigned acc = g_cgt;
        int chunk = 0;
        for (int c = 255; c >= 0; c--) {
            if (acc + csum[c] >= TOPN) { chunk = c; break; }
            acc += csum[c];
        }
        int bin = chunk * per;
        for (int j = per - 1; j >= 0; j--) {
            unsigned h = sh[chunk * per + j];
            if (acc + h >= TOPN) { bin = chunk * per + j; break; }
            acc += h;
        }
        if (level == 0) g_p1 = (unsigned)bin;
        else if (level == 1) g_p2 = (unsigned)bin;
        else g_p3 = (unsigned)bin;
        g_cgt = acc;
    }
}

// ---------------- level-1 / level-2 histogram refine passes ----------------
__global__ void k_hist2(const int* __restrict__ tgt) {
    __shared__ unsigned hh[2048];
    for (int i = threadIdx.x; i < 2048; i += blockDim.x) hh[i] = 0;
    __syncthreads();
    unsigned p1 = g_p1;
    int nt = gridDim.x * blockDim.x;
    for (int g = blockIdx.x * blockDim.x + threadIdx.x; g < NV4; g += nt) {
        int i0 = g << 2;
        float4 c = *(const float4*)(g_cos + i0);
        int4 t = *(const int4*)(tgt + i0);
        float cj[4] = {c.x, c.y, c.z, c.w};
        int ts[4] = {t.x, t.y, t.z, t.w};
#pragma unroll
        for (int j = 0; j < 4; j++) {
            if (ts[j] == 0) {
                unsigned k = fmono(cj[j]);
                if ((k >> 21) == p1) atomicAdd(&hh[(k >> 10) & 2047], 1u);
            }
        }
    }
    __syncthreads();
    for (int i = threadIdx.x; i < 2048; i += blockDim.x) {
        unsigned hv = hh[i];
        if (hv) atomicAdd(&g_histB[i], hv);
    }
}

__global__ void k_hist3(const int* __restrict__ tgt) {
    __shared__ unsigned hh[1024];
    for (int i = threadIdx.x; i < 1024; i += blockDim.x) hh[i] = 0;
    __syncthreads();
    unsigned pref = (g_p1 << 11) | g_p2;
    int nt = gridDim.x * blockDim.x;
    for (int g = blockIdx.x * blockDim.x + threadIdx.x; g < NV4; g += nt) {
        int i0 = g << 2;
        float4 c = *(const float4*)(g_cos + i0);
        int4 t = *(const int4*)(tgt + i0);
        float cj[4] = {c.x, c.y, c.z, c.w};
        int ts[4] = {t.x, t.y, t.z, t.w};
#pragma unroll
        for (int j = 0; j < 4; j++) {
            if (ts[j] == 0) {
                unsigned k = fmono(cj[j]);
                if ((k >> 10) == pref) atomicAdd(&hh[k & 1023], 1u);
            }
        }
    }
    __syncthreads();
    for (int i = threadIdx.x; i < 1024; i += blockDim.x) {
        unsigned hv = hh[i];
        if (hv) atomicAdd(&g_histC[i], hv);
    }
}

// ---------------- K8: mark > threshold, collect == threshold ----------------
__global__ void k_mark(const int* __restrict__ tgt) {
    unsigned thresh = (g_p1 << 21) | (g_p2 << 10) | g_p3;
    int nt = gridDim.x * blockDim.x;
    for (int g = blockIdx.x * blockDim.x + threadIdx.x; g < NV4; g += nt) {
        int i0 = g << 2;
        float4 c = *(const float4*)(g_cos + i0);
        int4 t = *(const int4*)(tgt + i0);
        float cj[4] = {c.x, c.y, c.z, c.w};
        int ts[4] = {t.x, t.y, t.z, t.w};
        unsigned hibits = 0;
#pragma unroll
        for (int j = 0; j < 4; j++) {
            if (ts[j] == 0) {
                unsigned k = fmono(cj[j]);
                if (k > thresh) hibits |= (1u << j);
                else if (k == thresh) {
                    unsigned idx = atomicAdd(&g_eqcnt, 1u);
                    if (idx < EQCAP) g_eq[idx] = i0 + j;
                }
            }
        }
        if (hibits)
            atomicOr(&g_hi[i0 >> 6], ((unsigned long long)hibits) << (i0 & 63));
    }
}

// ---------------- K9: tie resolution (lowest indices, like top_k) ----------
__global__ void k_eqres() {
    if (threadIdx.x != 0 || blockIdx.x != 0) return;
    int need = TOPN - (int)g_cgt;
    int n = (int)g_eqcnt; if (n > EQCAP) n = EQCAP;
    if (need <= 0) return;
    if (n <= need) {
        for (int j = 0; j < n; j++) {
            int i = g_eq[j];
            g_hi[i >> 6] |= (1ull << (i & 63));
        }
    } else {
        for (int r = 0; r < need; r++) {
            int best = 0x7fffffff, bj = -1;
            for (int j = 0; j < n; j++) {
                int vv = g_eq[j];
                if (vv < best) { best = vv; bj = j; }
            }
            g_eq[bj] = 0x7fffffff;
            g_hi[best >> 6] |= (1ull << (best & 63));
        }
    }
}

// ---------------- dilation (radius 10 box, separable, bitset) --------------
__global__ void k_dilw(int which) {
    const unsigned long long* in = which ? g_hi : g_pos;
    int r = blockIdx.x * blockDim.x + threadIdx.x;
    if (r >= NWORDS / 2) return;
    unsigned long long lo = in[2 * r], hi = in[2 * r + 1];
    unsigned long long olo = lo, ohi = hi;
#pragma unroll
    for (int s = 1; s <= 10; s++) {
        olo |= lo << s;
        ohi |= (hi << s) | (lo >> (64 - s));
        olo |= (lo >> s) | (hi << (64 - s));
        ohi |= hi >> s;
    }
    g_tmp1[2 * r] = olo; g_tmp1[2 * r + 1] = ohi;
}

__global__ void k_dilh() {
    int idx = blockIdx.x * blockDim.x + threadIdx.x;
    if (idx >= NWORDS) return;
    int k = idx & 1; int h = (idx >> 1) & 127; int bd = idx >> 8;
    int h0 = max(h - 10, 0), h1 = min(h + 10, 127);
    unsigned long long o = 0;
    for (int h2 = h0; h2 <= h1; h2++) o |= g_tmp1[(bd * 128 + h2) * 2 + k];
    g_tmp2[idx] = o;
}

__global__ void k_dild(int which) {
    int idx = blockIdx.x * blockDim.x + threadIdx.x;
    if (idx >= NWORDS) return;
    int k = idx & 1; int h = (idx >> 1) & 127; int d = (idx >> 8) & 127; int b = idx >> 15;
    int d0 = max(d - 10, 0), d1 = min(d + 10, 127);
    unsigned long long o = 0;
    for (int d2 = d0; d2 <= d1; d2++) o |= g_tmp2[((b * 128 + d2) * 128 + h) * 2 + k];
    unsigned long long* out = which ? g_hidil : g_posdil;
    out[idx] = o;
}

// ---------------- K16: masked sums for mis / neg losses --------------------
__global__ void k_maskred() {
    double vals[4] = {0.0, 0.0, 0.0, 0.0};  // easy_sum, easy_cnt, fneg_sum, fneg_cnt
    int nt = gridDim.x * blockDim.x;
    for (int g = blockIdx.x * blockDim.x + threadIdx.x; g < NV4; g += nt) {
        int i0 = g << 2;
        float4 c = *(const float4*)(g_cos + i0);
        int w = i0 >> 6; int shamt = i0 & 63;
        unsigned long long pw = g_pos[w] >> shamt;
        unsigned long long pd = g_posdil[w] >> shamt;
        unsigned long long hd = g_hidil[w] >> shamt;
        float cj[4] = {c.x, c.y, c.z, c.w};
#pragma unroll
        for (int j = 0; j < 4; j++) {
            if (!((pw >> j) & 1ull)) {
                float rc = fmaxf(cj[j], 0.0f);
                if ((pd >> j) & 1ull) { vals[0] += (double)rc; vals[1] += 1.0; }
                if ((hd >> j) & 1ull) { vals[2] += (double)rc; vals[3] += 1.0; }
            }
        }
    }
    block_accumulate<4>(vals, 27);
}

// ---------------- K17: final scalar ----------------
__global__ void k_finalize(float* out) {
    if (threadIdx.x != 0 || blockIdx.x != 0) return;
    double ce = -g_red[0] / (double)NV;
    double dcl = 0.0;
    for (int c = 1; c < 3; c++) {
        double tp = g_red[4 + c];
        double fp = g_red[1 + c] - tp;
        double fn = g_red[7 + c] - tp;
        dcl += (2.0 * tp + 1e-5) / fmax(2.0 * tp + fp + fn + 1e-5, 1e-8);
    }
    double dc_loss = -dcl * 0.5;
    double cnt1 = g_red[8];
    double pos_loss = (cnt1 > 0.0) ? (cnt1 - g_red[10]) / cnt1 : 0.0;
    double mis_loss = (g_red[28] > 0.0) ? g_red[27] / g_red[28] : 0.0;
    double neg_loss = (g_red[30] > 0.0) ? g_red[29] / g_red[30] : 0.0;
    out[0] = (float)(ce + dc_loss + 5.0 * (pos_loss + mis_loss + neg_loss));
}

// ---------------- launch ----------------
extern "C" void kernel_launch(void* const* d_in, const int* in_sizes, int n_in,
                              void* d_out, int out_size) {
    const float* feat = (const float*)d_in[0];
    const float* net  = (const float*)d_in[1];
    const int*   tgt  = (const int*)d_in[2];
    float* out = (float*)d_out;

    k_zero<<<256, 256>>>();
    k_cedice<<<1024, 256>>>(net, tgt);
    k_featsum<<<1024, 256>>>(feat, tgt);
    k_stdn<<<1, 32>>>();
    k_cos<<<1024, 256>>>(feat, tgt);
    k_select<<<1, 256>>>(0);
    k_hist2<<<512, 256>>>(tgt);
    k_select<<<1, 256>>>(1);
    k_hist3<<<512, 256>>>(tgt);
    k_select<<<1, 256>>>(2);
    k_mark<<<512, 256>>>(tgt);
    k_eqres<<<1, 32>>>();
    // dilate pos
    k_dilw<<<128, 256>>>(0);
    k_dilh<<<256, 256>>>();
    k_dild<<<256, 256>>>(0);
    // dilate hi
    k_dilw<<<128, 256>>>(1);
    k_dilh<<<256, 256>>>();
    k_dild<<<256, 256>>>(1);
    k_maskred<<<512, 256>>>();
    k_finalize<<<1, 32>>>(out);
}

// round 10
// speedup vs baseline: 2.2294x; 2.2294x over previous
#include <cuda_runtime.h>
#include <math.h>

// Shapes: feature (2,16,128,128,128) f32, net_output (2,3,128,128,128) f32,
// target (2,1,128,128,128) i32. Output: scalar f32.
#define VV   (128*128*128)      /* 2^21 voxels per batch */
#define NV   (2*VV)             /* 4,194,304 */
#define NV4  (NV/4)
#define NWORDS (NV/64)          /* 65536 bitset words */
#define TOPN 250
#define EQCAP 4096

typedef unsigned long long u64;

// ---------------- device scratch ----------------
// g_redf layout: 0 ce_sum | 1..3 sum_p[c] | 4..6 tp[c] | 7..9 cnt[c]
//                10 pos_cos_sum | 11..26 featsum[16]
//                27 easy_sum | 28 easy_cnt | 29 fneg_sum | 30 fneg_cnt
__device__ float g_redf[32];
__device__ float g_stdn[16];
__device__ unsigned g_histA[2048];
__device__ unsigned g_histB[2048];
__device__ unsigned g_histC[1024];
__device__ unsigned g_p1, g_p2, g_p3, g_cgt, g_eqcnt;
__device__ int g_eq[EQCAP];
__device__ float g_cos[NV];
__device__ u64 g_pos[NWORDS];
__device__ u64 g_neg[NWORDS];
__device__ u64 g_hi[NWORDS];
__device__ u64 g_tmp2[NWORDS];
__device__ u64 g_posdil[NWORDS];
__device__ u64 g_hidil[NWORDS];

// ---------------- helpers ----------------
__device__ __forceinline__ unsigned fmono(float f) {
    unsigned u = __float_as_uint(f);
    return (u & 0x80000000u) ? ~u : (u | 0x80000000u);
}

__device__ __forceinline__ float warp_sumf(float v) {
#pragma unroll
    for (int o = 16; o; o >>= 1) v += __shfl_down_sync(0xffffffffu, v, o);
    return v;
}

template<int N>
__device__ __forceinline__ void block_accumulate(const float* vals, int base) {
    __shared__ float sh[N];
    if (threadIdx.x < N) sh[threadIdx.x] = 0.0f;
    __syncthreads();
    int lane = threadIdx.x & 31;
#pragma unroll
    for (int k = 0; k < N; k++) {
        float w = warp_sumf(vals[k]);
        if (lane == 0 && w != 0.0f) atomicAdd(&sh[k], w);
    }
    __syncthreads();
    if (threadIdx.x < N && sh[threadIdx.x] != 0.0f)
        atomicAdd(&g_redf[base + threadIdx.x], sh[threadIdx.x]);
}

// ---------------- K0: zero scratch ----------------
__global__ void k_zero() {
    int i = blockIdx.x * blockDim.x + threadIdx.x;
    if (i < 2048) { g_histA[i] = 0; g_histB[i] = 0; }
    if (i < 1024) { g_histC[i] = 0; }
    if (i < NWORDS) { g_pos[i] = 0ull; g_neg[i] = 0ull; g_hi[i] = 0ull; }
    if (i < 32) g_redf[i] = 0.0f;
    if (i == 0) { g_cgt = 0u; g_eqcnt = 0u; }
}

// ---------------- K1: CE + Dice statistics (all-float, no local mem) -------
__global__ __launch_bounds__(256) void k_cedice(const float* __restrict__ net,
                                                const int* __restrict__ tgt) {
    float ce = 0, sp0 = 0, sp1 = 0, sp2 = 0;
    float tp0 = 0, tp1 = 0, tp2 = 0, c0 = 0, c1 = 0, c2 = 0;
    int nt = gridDim.x * blockDim.x;
    for (int g = blockIdx.x * blockDim.x + threadIdx.x; g < NV4; g += nt) {
        int i0 = g << 2;
        int b = i0 >> 21; int v = i0 & (VV - 1);
        const float* base = net + (size_t)b * 3 * VV + v;
        float4 x0 = *(const float4*)(base);
        float4 x1 = *(const float4*)(base + VV);
        float4 x2 = *(const float4*)(base + 2 * (size_t)VV);
        int4 tt = *(const int4*)(tgt + i0);
        float a0[4] = {x0.x, x0.y, x0.z, x0.w};
        float a1[4] = {x1.x, x1.y, x1.z, x1.w};
        float a2[4] = {x2.x, x2.y, x2.z, x2.w};
        int ts[4] = {tt.x, tt.y, tt.z, tt.w};
#pragma unroll
        for (int j = 0; j < 4; j++) {
            float xa = a0[j], xb = a1[j], xc = a2[j];
            float m = fmaxf(xa, fmaxf(xb, xc));
            float e0 = __expf(xa - m), e1 = __expf(xb - m), e2 = __expf(xc - m);
            float ssum = e0 + e1 + e2;
            float ls = __logf(ssum);
            int t = ts[j];
            float xt = (t == 0) ? xa : ((t == 1) ? xb : xc);
            ce += xt - m - ls;
            float inv = __frcp_rn(ssum);
            float p0 = e0 * inv, p1 = e1 * inv, p2 = e2 * inv;
            sp0 += p0; sp1 += p1; sp2 += p2;
            float pt = (t == 0) ? p0 : ((t == 1) ? p1 : p2);
            tp0 += (t == 0) ? pt : 0.0f;  c0 += (t == 0) ? 1.0f : 0.0f;
            tp1 += (t == 1) ? pt : 0.0f;  c1 += (t == 1) ? 1.0f : 0.0f;
            tp2 += (t == 2) ? pt : 0.0f;  c2 += (t == 2) ? 1.0f : 0.0f;
        }
    }
    float acc[10] = {ce, sp0, sp1, sp2, tp0, tp1, tp2, c0, c1, c2};
    block_accumulate<10>(acc, 0);
}

// ---------------- K2: per-channel feature sum over positives ---------------
__global__ __launch_bounds__(256) void k_featsum(const float* __restrict__ feat,
                                                 const int* __restrict__ tgt) {
    float s[16];
#pragma unroll
    for (int c = 0; c < 16; c++) s[c] = 0.0f;
    int nt = gridDim.x * blockDim.x;
    for (int g = blockIdx.x * blockDim.x + threadIdx.x; g < NV4; g += nt) {
        int i0 = g << 2;
        int b = i0 >> 21; int v = i0 & (VV - 1);
        int4 tt = *(const int4*)(tgt + i0);
        float m0 = (tt.x == 1) ? 1.0f : 0.0f;
        float m1 = (tt.y == 1) ? 1.0f : 0.0f;
        float m2 = (tt.z == 1) ? 1.0f : 0.0f;
        float m3 = (tt.w == 1) ? 1.0f : 0.0f;
        const float* fb = feat + (size_t)b * 16 * VV + v;
#pragma unroll
        for (int c = 0; c < 16; c++) {
            float4 x = *(const float4*)(fb + (size_t)c * VV);
            s[c] += x.x * m0 + x.y * m1 + x.z * m2 + x.w * m3;
        }
    }
    block_accumulate<16>(s, 11);
}

// ---------------- K3: normalize positive-mean direction (float, 1 warp) ----
// std_n = mean/||mean|| == sum/||sum|| (count cancels); zeros if no positives.
__global__ void k_stdn() {
    int c = threadIdx.x;
    float s = (c < 16) ? g_redf[11 + c] : 0.0f;
    float sq = s * s;
#pragma unroll
    for (int o = 16; o; o >>= 1) sq += __shfl_xor_sync(0xffffffffu, sq, o);
    float nrm = sqrtf(sq);
    float inv = (nrm > 1e-30f) ? __frcp_rn(nrm) : 0.0f;
    if (c < 16) g_stdn[c] = s * inv;
}

// ---------------- K4: cos map + pos/neg bitsets + pos sum + level-0 hist ---
__global__ __launch_bounds__(256) void k_cos(const float* __restrict__ feat,
                                             const int* __restrict__ tgt) {
    __shared__ unsigned hh[2048];
    for (int i = threadIdx.x; i < 2048; i += blockDim.x) hh[i] = 0;
    __syncthreads();
    float sn[16];
#pragma unroll
    for (int c = 0; c < 16; c++) sn[c] = g_stdn[c];
    float psum = 0.0f;
    int nt = gridDim.x * blockDim.x;
    for (int g = blockIdx.x * blockDim.x + threadIdx.x; g < NV4; g += nt) {
        int i0 = g << 2;
        int b = i0 >> 21; int v = i0 & (VV - 1);
        const float* fb = feat + (size_t)b * 16 * VV + v;
        float d0 = 0, d1 = 0, d2 = 0, d3 = 0;
        float n0 = 0, n1 = 0, n2 = 0, n3 = 0;
#pragma unroll
        for (int c = 0; c < 16; c++) {
            float4 x = *(const float4*)(fb + (size_t)c * VV);
            d0 += x.x * sn[c]; n0 += x.x * x.x;
            d1 += x.y * sn[c]; n1 += x.y * x.y;
            d2 += x.z * sn[c]; n2 += x.z * x.z;
            d3 += x.w * sn[c]; n3 += x.w * x.w;
        }
        float4 cs;
        cs.x = d0 / fmaxf(sqrtf(n0), 1e-12f);
        cs.y = d1 / fmaxf(sqrtf(n1), 1e-12f);
        cs.z = d2 / fmaxf(sqrtf(n2), 1e-12f);
        cs.w = d3 / fmaxf(sqrtf(n3), 1e-12f);
        *(float4*)(g_cos + i0) = cs;
        int4 tt = *(const int4*)(tgt + i0);
        float cj[4] = {cs.x, cs.y, cs.z, cs.w};
        int ts[4] = {tt.x, tt.y, tt.z, tt.w};
        unsigned posbits = 0, negbits = 0;
#pragma unroll
        for (int j = 0; j < 4; j++) {
            if (ts[j] == 1) { psum += cj[j]; posbits |= (1u << j); }
            else if (ts[j] == 0) {
                negbits |= (1u << j);
                atomicAdd(&hh[fmono(cj[j]) >> 21], 1u);
            }
        }
        if (posbits) atomicOr(&g_pos[i0 >> 6], ((u64)posbits) << (i0 & 63));
        if (negbits) atomicOr(&g_neg[i0 >> 6], ((u64)negbits) << (i0 & 63));
    }
    __syncthreads();
    for (int i = threadIdx.x; i < 2048; i += blockDim.x) {
        unsigned hv = hh[i];
        if (hv) atomicAdd(&g_histA[i], hv);
    }
    float one[1] = {psum};
    block_accumulate<1>(one, 10);
}

// ---------------- radix-select one level (single block) ----------------
__global__ void k_select(int level) {
    __shared__ unsigned sh[2048];
    __shared__ unsigned csum[256];
    const unsigned* hist = (level == 0) ? g_histA : ((level == 1) ? g_histB : g_histC);
    int nbins = (level == 2) ? 1024 : 2048;
    int per = nbins / 256;
    for (int i = threadIdx.x; i < nbins; i += 256) sh[i] = hist[i];
    __syncthreads();
    unsigned s = 0;
    for (int j = 0; j < per; j++) s += sh[threadIdx.x * per + j];
    csum[threadIdx.x] = s;
    __syncthreads();
    if (threadIdx.x == 0) {
        unsigned acc = g_cgt;
        int chunk = 0;
        for (int c = 255; c >= 0; c--) {
            if (acc + csum[c] >= TOPN) { chunk = c; break; }
            acc += csum[c];
        }
        int bin = chunk * per;
        for (int j = per - 1; j >= 0; j--) {
            unsigned h = sh[chunk * per + j];
            if (acc + h >= TOPN) { bin = chunk * per + j; break; }
            acc += h;
        }
        if (level == 0) g_p1 = (unsigned)bin;
        else if (level == 1) g_p2 = (unsigned)bin;
        else g_p3 = (unsigned)bin;
        g_cgt = acc;
    }
}

// ---------------- level-1 / level-2 refine passes (bitset-gated) -----------
__global__ __launch_bounds__(256) void k_hist2() {
    __shared__ unsigned hh[2048];
    for (int i = threadIdx.x; i < 2048; i += blockDim.x) hh[i] = 0;
    __syncthreads();
    unsigned p1 = g_p1;
    int nt = gridDim.x * blockDim.x;
    for (int g = blockIdx.x * blockDim.x + threadIdx.x; g < NV4; g += nt) {
        int i0 = g << 2;
        unsigned nb = (unsigned)(g_neg[i0 >> 6] >> (i0 & 63)) & 0xFu;
        if (!nb) continue;
        float4 c = *(const float4*)(g_cos + i0);
        float cj[4] = {c.x, c.y, c.z, c.w};
#pragma unroll
        for (int j = 0; j < 4; j++) {
            if ((nb >> j) & 1u) {
                unsigned k = fmono(cj[j]);
                if ((k >> 21) == p1) atomicAdd(&hh[(k >> 10) & 2047], 1u);
            }
        }
    }
    __syncthreads();
    for (int i = threadIdx.x; i < 2048; i += blockDim.x) {
        unsigned hv = hh[i];
        if (hv) atomicAdd(&g_histB[i], hv);
    }
}

__global__ __launch_bounds__(256) void k_hist3() {
    __shared__ unsigned hh[1024];
    for (int i = threadIdx.x; i < 1024; i += blockDim.x) hh[i] = 0;
    __syncthreads();
    unsigned pref = (g_p1 << 11) | g_p2;
    int nt = gridDim.x * blockDim.x;
    for (int g = blockIdx.x * blockDim.x + threadIdx.x; g < NV4; g += nt) {
        int i0 = g << 2;
        unsigned nb = (unsigned)(g_neg[i0 >> 6] >> (i0 & 63)) & 0xFu;
        if (!nb) continue;
        float4 c = *(const float4*)(g_cos + i0);
        float cj[4] = {c.x, c.y, c.z, c.w};
#pragma unroll
        for (int j = 0; j < 4; j++) {
            if ((nb >> j) & 1u) {
                unsigned k = fmono(cj[j]);
                if ((k >> 10) == pref) atomicAdd(&hh[k & 1023], 1u);
            }
        }
    }
    __syncthreads();
    for (int i = threadIdx.x; i < 1024; i += blockDim.x) {
        unsigned hv = hh[i];
        if (hv) atomicAdd(&g_histC[i], hv);
    }
}

// ---------------- K8: mark > threshold, collect == threshold ---------------
__global__ __launch_bounds__(256) void k_mark() {
    unsigned thresh = (g_p1 << 21) | (g_p2 << 10) | g_p3;
    int nt = gridDim.x * blockDim.x;
    for (int g = blockIdx.x * blockDim.x + threadIdx.x; g < NV4; g += nt) {
        int i0 = g << 2;
        unsigned nb = (unsigned)(g_neg[i0 >> 6] >> (i0 & 63)) & 0xFu;
        if (!nb) continue;
        float4 c = *(const float4*)(g_cos + i0);
        float cj[4] = {c.x, c.y, c.z, c.w};
        unsigned hibits = 0;
#pragma unroll
        for (int j = 0; j < 4; j++) {
            if ((nb >> j) & 1u) {
                unsigned k = fmono(cj[j]);
                if (k > thresh) hibits |= (1u << j);
                else if (k == thresh) {
                    unsigned idx = atomicAdd(&g_eqcnt, 1u);
                    if (idx < EQCAP) g_eq[idx] = i0 + j;
                }
            }
        }
        if (hibits) atomicOr(&g_hi[i0 >> 6], ((u64)hibits) << (i0 & 63));
    }
}

// ---------------- K9: tie resolution (lowest indices, like top_k) ----------
__global__ void k_eqres() {
    if (threadIdx.x != 0 || blockIdx.x != 0) return;
    int need = TOPN - (int)g_cgt;
    int n = (int)g_eqcnt; if (n > EQCAP) n = EQCAP;
    if (need <= 0) return;
    if (n <= need) {
        for (int j = 0; j < n; j++) {
            int i = g_eq[j];
            g_hi[i >> 6] |= (1ull << (i & 63));
        }
    } else {
        for (int r = 0; r < need; r++) {
            int best = 0x7fffffff, bj = -1;
            for (int j = 0; j < n; j++) {
                int vv = g_eq[j];
                if (vv < best) { best = vv; bj = j; }
            }
            g_eq[bj] = 0x7fffffff;
            g_hi[best >> 6] |= (1ull << (best & 63));
        }
    }
}

// ---------------- fused W+H dilation (radius 10, per (b,d) slice) ----------
__global__ void k_dilwh(int which) {
    const u64* in = which ? g_hi : g_pos;
    __shared__ u64 sh[128][2];
    int bd = blockIdx.x; int h = threadIdx.x;
    u64 lo = in[(bd * 128 + h) * 2];
    u64 hi = in[(bd * 128 + h) * 2 + 1];
    u64 olo = lo, ohi = hi;
#pragma unroll
    for (int s = 1; s <= 10; s++) {
        olo |= lo << s;
        ohi |= (hi << s) | (lo >> (64 - s));
        olo |= (lo >> s) | (hi << (64 - s));
        ohi |= hi >> s;
    }
    sh[h][0] = olo; sh[h][1] = ohi;
    __syncthreads();
    int h0 = max(h - 10, 0), h1 = min(h + 10, 127);
    u64 rlo = 0, rhi = 0;
    for (int h2 = h0; h2 <= h1; h2++) { rlo |= sh[h2][0]; rhi |= sh[h2][1]; }
    g_tmp2[(bd * 128 + h) * 2] = rlo;
    g_tmp2[(bd * 128 + h) * 2 + 1] = rhi;
}

__global__ void k_dild(int which) {
    int idx = blockIdx.x * blockDim.x + threadIdx.x;
    if (idx >= NWORDS) return;
    int k = idx & 1; int h = (idx >> 1) & 127; int d = (idx >> 8) & 127; int b = idx >> 15;
    int d0 = max(d - 10, 0), d1 = min(d + 10, 127);
    u64 o = 0;
    for (int d2 = d0; d2 <= d1; d2++) o |= g_tmp2[((b * 128 + d2) * 128 + h) * 2 + k];
    u64* out = which ? g_hidil : g_posdil;
    out[idx] = o;
}

// ---------------- K16: masked sums for mis / neg losses --------------------
__global__ __launch_bounds__(256) void k_maskred() {
    float esum = 0, ecnt = 0, fsum = 0, fcnt = 0;
    int nt = gridDim.x * blockDim.x;
    for (int g = blockIdx.x * blockDim.x + threadIdx.x; g < NV4; g += nt) {
        int i0 = g << 2;
        int w = i0 >> 6; int shamt = i0 & 63;
        u64 pw = g_pos[w] >> shamt;
        u64 pd = g_posdil[w] >> shamt;
        u64 hd = g_hidil[w] >> shamt;
        unsigned any = (unsigned)((pd | hd) & ~pw) & 0xFu;
        if (!any) continue;
        float4 c = *(const float4*)(g_cos + i0);
        float cj[4] = {c.x, c.y, c.z, c.w};
#pragma unroll
        for (int j = 0; j < 4; j++) {
            if (!((pw >> j) & 1ull)) {
                float rc = fmaxf(cj[j], 0.0f);
                if ((pd >> j) & 1ull) { esum += rc; ecnt += 1.0f; }
                if ((hd >> j) & 1ull) { fsum += rc; fcnt += 1.0f; }
            }
        }
    }
    float vals[4] = {esum, ecnt, fsum, fcnt};
    block_accumulate<4>(vals, 27);
}

// ---------------- K17: final scalar ----------------
__global__ void k_finalize(float* out) {
    if (threadIdx.x != 0 || blockIdx.x != 0) return;
    double ce = -(double)g_redf[0] / (double)NV;
    double dcl = 0.0;
    for (int c = 1; c < 3; c++) {
        double tp = g_redf[4 + c];
        double fp = (double)g_redf[1 + c] - tp;
        double fn = (double)g_redf[7 + c] - tp;
        dcl += (2.0 * tp + 1e-5) / fmax(2.0 * tp + fp + fn + 1e-5, 1e-8);
    }
    double dc_loss = -dcl * 0.5;
    double cnt1 = g_redf[8];
    double pos_loss = (cnt1 > 0.0) ? (cnt1 - (double)g_redf[10]) / cnt1 : 0.0;
    double mis_loss = (g_redf[28] > 0.0f) ? (double)g_redf[27] / (double)g_redf[28] : 0.0;
    double neg_loss = (g_redf[30] > 0.0f) ? (double)g_redf[29] / (double)g_redf[30] : 0.0;
    out[0] = (float)(ce + dc_loss + 5.0 * (pos_loss + mis_loss + neg_loss));
}

// ---------------- launch ----------------
extern "C" void kernel_launch(void* const* d_in, const int* in_sizes, int n_in,
                              void* d_out, int out_size) {
    const float* feat = (const float*)d_in[0];
    const float* net  = (const float*)d_in[1];
    const int*   tgt  = (const int*)d_in[2];
    float* out = (float*)d_out;

    k_zero<<<256, 256>>>();
    k_cedice<<<2048, 256>>>(net, tgt);
    k_featsum<<<2048, 256>>>(feat, tgt);
    k_stdn<<<1, 32>>>();
    k_cos<<<2048, 256>>>(feat, tgt);
    // pos dilation (independent of top-k; placed here in stream order)
    k_dilwh<<<256, 128>>>(0);
    k_dild<<<256, 256>>>(0);
    // top-250 negative selection (3-level radix)
    k_select<<<1, 256>>>(0);
    k_hist2<<<1024, 256>>>();
    k_select<<<1, 256>>>(1);
    k_hist3<<<1024, 256>>>();
    k_select<<<1, 256>>>(2);
    k_mark<<<1024, 256>>>();
    k_eqres<<<1, 32>>>();
    // hi dilation
    k_dilwh<<<256, 128>>>(1);
    k_dild<<<256, 256>>>(1);
    k_maskred<<<1024, 256>>>();
    k_finalize<<<1, 32>>>(out);
}

// round 14
// speedup vs baseline: 2.4714x; 1.1086x over previous
#include <cuda_runtime.h>
#include <math.h>

// Shapes: feature (2,16,128,128,128) f32, net_output (2,3,128,128,128) f32,
// target (2,1,128,128,128) i32. Output: scalar f32.
#define VV   (128*128*128)      /* 2^21 voxels per batch */
#define NV   (2*VV)             /* 4,194,304 */
#define NV4  (NV/4)
#define NWORDS (NV/64)          /* 65536 bitset words */
#define TOPN 250
#define CCAP 65536
#define EQCAP 2048

typedef unsigned long long u64;

// ---------------- device scratch ----------------
// g_redf layout: 0 ce_sum | 1..3 sum_p[c] | 4..6 tp[c] | 7..9 cnt[c]
//                10 pos_cos_sum | 11..26 featsum[16]
//                27 easy_sum | 28 easy_cnt | 29 fneg_sum | 30 fneg_cnt
__device__ float g_redf[32];
__device__ unsigned g_histA[2048];
__device__ unsigned g_ccnt, g_done;
__device__ unsigned g_ckey[CCAP];
__device__ int g_cidx[CCAP];
__device__ float g_cos[NV];
__device__ u64 g_pos[NWORDS];
__device__ u64 g_neg[NWORDS];
__device__ u64 g_hi[NWORDS];
__device__ u64 g_tmpA[2 * NWORDS];
__device__ u64 g_posdil[NWORDS];
__device__ u64 g_hidil[NWORDS];

// ---------------- helpers ----------------
__device__ __forceinline__ unsigned fmono(float f) {
    unsigned u = __float_as_uint(f);
    return (u & 0x80000000u) ? ~u : (u | 0x80000000u);
}

__device__ __forceinline__ float warp_sumf(float v) {
#pragma unroll
    for (int o = 16; o; o >>= 1) v += __shfl_down_sync(0xffffffffu, v, o);
    return v;
}

template<int N>
__device__ __forceinline__ void block_accumulate(const float* vals, int base) {
    __shared__ float sh[N];
    if (threadIdx.x < N) sh[threadIdx.x] = 0.0f;
    __syncthreads();
    int lane = threadIdx.x & 31;
#pragma unroll
    for (int k = 0; k < N; k++) {
        float w = warp_sumf(vals[k]);
        if (lane == 0 && w != 0.0f) atomicAdd(&sh[k], w);
    }
    __syncthreads();
    if (threadIdx.x < N && sh[threadIdx.x] != 0.0f)
        atomicAdd(&g_redf[base + threadIdx.x], sh[threadIdx.x]);
}

// ---------------- K0: zero scratch ----------------
__global__ void k_zero() {
    int i = blockIdx.x * blockDim.x + threadIdx.x;
    if (i < 2048) g_histA[i] = 0;
    if (i < NWORDS) { g_pos[i] = 0ull; g_neg[i] = 0ull; g_hi[i] = 0ull; }
    if (i < 32) g_redf[i] = 0.0f;
    if (i == 0) { g_ccnt = 0u; g_done = 0u; }
}

// ---------------- K1: CE + Dice stats + per-channel positive feature sums --
__global__ __launch_bounds__(256) void k_main(const float* __restrict__ net,
                                              const float* __restrict__ feat,
                                              const int* __restrict__ tgt) {
    float ce = 0, sp0 = 0, sp1 = 0, sp2 = 0;
    float tp0 = 0, tp1 = 0, tp2 = 0, c0 = 0, c1 = 0, c2 = 0;
    float s[16];
#pragma unroll
    for (int c = 0; c < 16; c++) s[c] = 0.0f;
    int nt = gridDim.x * blockDim.x;
    for (int g = blockIdx.x * blockDim.x + threadIdx.x; g < NV4; g += nt) {
        int i0 = g << 2;
        int b = i0 >> 21; int v = i0 & (VV - 1);
        int4 tt = *(const int4*)(tgt + i0);
        // --- CE/Dice part ---
        const float* base = net + (size_t)b * 3 * VV + v;
        float4 x0 = *(const float4*)(base);
        float4 x1 = *(const float4*)(base + VV);
        float4 x2 = *(const float4*)(base + 2 * (size_t)VV);
        float a0[4] = {x0.x, x0.y, x0.z, x0.w};
        float a1[4] = {x1.x, x1.y, x1.z, x1.w};
        float a2[4] = {x2.x, x2.y, x2.z, x2.w};
        int ts[4] = {tt.x, tt.y, tt.z, tt.w};
#pragma unroll
        for (int j = 0; j < 4; j++) {
            float xa = a0[j], xb = a1[j], xc = a2[j];
            float m = fmaxf(xa, fmaxf(xb, xc));
            float e0 = __expf(xa - m), e1 = __expf(xb - m), e2 = __expf(xc - m);
            float ssum = e0 + e1 + e2;
            float ls = __logf(ssum);
            int t = ts[j];
            float xt = (t == 0) ? xa : ((t == 1) ? xb : xc);
            ce += xt - m - ls;
            float inv = __frcp_rn(ssum);
            float p0 = e0 * inv, p1 = e1 * inv, p2 = e2 * inv;
            sp0 += p0; sp1 += p1; sp2 += p2;
            float pt = (t == 0) ? p0 : ((t == 1) ? p1 : p2);
            tp0 += (t == 0) ? pt : 0.0f;  c0 += (t == 0) ? 1.0f : 0.0f;
            tp1 += (t == 1) ? pt : 0.0f;  c1 += (t == 1) ? 1.0f : 0.0f;
            tp2 += (t == 2) ? pt : 0.0f;  c2 += (t == 2) ? 1.0f : 0.0f;
        }
        // --- featsum part ---
        float m0 = (tt.x == 1) ? 1.0f : 0.0f;
        float m1 = (tt.y == 1) ? 1.0f : 0.0f;
        float m2 = (tt.z == 1) ? 1.0f : 0.0f;
        float m3 = (tt.w == 1) ? 1.0f : 0.0f;
        const float* fb = feat + (size_t)b * 16 * VV + v;
#pragma unroll
        for (int c = 0; c < 16; c++) {
            float4 x = *(const float4*)(fb + (size_t)c * VV);
            s[c] += x.x * m0 + x.y * m1 + x.z * m2 + x.w * m3;
        }
    }
    float acc[10] = {ce, sp0, sp1, sp2, tp0, tp1, tp2, c0, c1, c2};
    block_accumulate<10>(acc, 0);
    block_accumulate<16>(s, 11);
}

// ---------------- K2: cos map + bitsets + pos sum + level-0 hist -----------
// std_n computed inline: sum/||sum|| == mean/||mean|| (count cancels).
__global__ __launch_bounds__(256) void k_cos(const float* __restrict__ feat,
                                             const int* __restrict__ tgt) {
    __shared__ unsigned hh[2048];
    __shared__ float s_sum[16];
    for (int i = threadIdx.x; i < 2048; i += blockDim.x) hh[i] = 0;
    if (threadIdx.x < 16) s_sum[threadIdx.x] = g_redf[11 + threadIdx.x];
    __syncthreads();
    float nrm2 = 0.0f;
#pragma unroll
    for (int c = 0; c < 16; c++) nrm2 += s_sum[c] * s_sum[c];
    float nrm = sqrtf(nrm2);
    float rinv = (nrm > 1e-30f) ? __frcp_rn(nrm) : 0.0f;
    float sn[16];
#pragma unroll
    for (int c = 0; c < 16; c++) sn[c] = s_sum[c] * rinv;

    float psum = 0.0f;
    int nt = gridDim.x * blockDim.x;
    for (int g = blockIdx.x * blockDim.x + threadIdx.x; g < NV4; g += nt) {
        int i0 = g << 2;
        int b = i0 >> 21; int v = i0 & (VV - 1);
        const float* fb = feat + (size_t)b * 16 * VV + v;
        float d0 = 0, d1 = 0, d2 = 0, d3 = 0;
        float n0 = 0, n1 = 0, n2 = 0, n3 = 0;
#pragma unroll
        for (int c = 0; c < 16; c++) {
            float4 x = *(const float4*)(fb + (size_t)c * VV);
            d0 += x.x * sn[c]; n0 += x.x * x.x;
            d1 += x.y * sn[c]; n1 += x.y * x.y;
            d2 += x.z * sn[c]; n2 += x.z * x.z;
            d3 += x.w * sn[c]; n3 += x.w * x.w;
        }
        float4 cs;
        cs.x = d0 / fmaxf(sqrtf(n0), 1e-12f);
        cs.y = d1 / fmaxf(sqrtf(n1), 1e-12f);
        cs.z = d2 / fmaxf(sqrtf(n2), 1e-12f);
        cs.w = d3 / fmaxf(sqrtf(n3), 1e-12f);
        *(float4*)(g_cos + i0) = cs;
        int4 tt = *(const int4*)(tgt + i0);
        float cj[4] = {cs.x, cs.y, cs.z, cs.w};
        int ts[4] = {tt.x, tt.y, tt.z, tt.w};
        unsigned posbits = 0, negbits = 0;
#pragma unroll
        for (int j = 0; j < 4; j++) {
            if (ts[j] == 1) { psum += cj[j]; posbits |= (1u << j); }
            else if (ts[j] == 0) {
                negbits |= (1u << j);
                atomicAdd(&hh[fmono(cj[j]) >> 21], 1u);
            }
        }
        if (posbits) atomicOr(&g_pos[i0 >> 6], ((u64)posbits) << (i0 & 63));
        if (negbits) atomicOr(&g_neg[i0 >> 6], ((u64)negbits) << (i0 & 63));
    }
    __syncthreads();
    for (int i = threadIdx.x; i < 2048; i += blockDim.x) {
        unsigned hv = hh[i];
        if (hv) atomicAdd(&g_histA[i], hv);
    }
    float one[1] = {psum};
    block_accumulate<1>(one, 10);
}

// ---------------- K3: collect candidates with level-0 bin >= p1 ------------
__global__ __launch_bounds__(256) void k_collect() {
    __shared__ unsigned sh[2048];
    __shared__ unsigned csum[256];
    __shared__ unsigned s_p1;
    int tid = threadIdx.x;
    for (int i = tid; i < 2048; i += 256) sh[i] = g_histA[i];
    __syncthreads();
    unsigned s = 0;
    for (int j = 0; j < 8; j++) s += sh[tid * 8 + j];
    csum[tid] = s;
    __syncthreads();
    if (tid == 0) {
        unsigned acc = 0; int chunk = 0;
        for (int c = 255; c >= 0; c--) {
            if (acc + csum[c] >= TOPN) { chunk = c; break; }
            acc += csum[c];
        }
        int bin = chunk * 8;
        for (int j = 7; j >= 0; j--) {
            unsigned h = sh[chunk * 8 + j];
            if (acc + h >= TOPN) { bin = chunk * 8 + j; break; }
            acc += h;
        }
        s_p1 = (unsigned)bin;
    }
    __syncthreads();
    unsigned p1 = s_p1;
    int nt = gridDim.x * blockDim.x;
    for (int g = blockIdx.x * blockDim.x + tid; g < NV4; g += nt) {
        int i0 = g << 2;
        unsigned nb = (unsigned)(g_neg[i0 >> 6] >> (i0 & 63)) & 0xFu;
        if (!nb) continue;
        float4 c = *(const float4*)(g_cos + i0);
        float cj[4] = {c.x, c.y, c.z, c.w};
#pragma unroll
        for (int j = 0; j < 4; j++) {
            if ((nb >> j) & 1u) {
                unsigned k = fmono(cj[j]);
                if ((k >> 21) >= p1) {
                    unsigned id = atomicAdd(&g_ccnt, 1u);
                    if (id < CCAP) { g_ckey[id] = k; g_cidx[id] = i0 + j; }
                }
            }
        }
    }
}

// ---------------- K4: single-block top-250 among candidates ----------------
// List contains ALL negatives with key >= start of bin p1, hence all top-250.
__global__ __launch_bounds__(256) void k_topk() {
    __shared__ unsigned hh[2048];
    __shared__ unsigned csum[256];
    __shared__ unsigned s_q, s_acc;
    __shared__ int s_eq[EQCAP];
    __shared__ unsigned s_eqn;
    int tid = threadIdx.x;
    int n = (int)min(g_ccnt, (unsigned)CCAP);

    // ---- level 1: top 11 bits ----
    for (int i = tid; i < 2048; i += 256) hh[i] = 0;
    __syncthreads();
    for (int i = tid; i < n; i += 256) atomicAdd(&hh[g_ckey[i] >> 21], 1u);
    __syncthreads();
    unsigned sum1 = 0;
    for (int j = 0; j < 8; j++) sum1 += hh[tid * 8 + j];
    csum[tid] = sum1;
    __syncthreads();
    if (tid == 0) {
        unsigned acc = 0; int chunk = 0;
        for (int c = 255; c >= 0; c--) {
            if (acc + csum[c] >= TOPN) { chunk = c; break; }
            acc += csum[c];
        }
        int bin = chunk * 8;
        for (int j = 7; j >= 0; j--) {
            unsigned h = hh[chunk * 8 + j];
            if (acc + h >= TOPN) { bin = chunk * 8 + j; break; }
            acc += h;
        }
        s_q = (unsigned)bin; s_acc = acc;
    }
    __syncthreads();
    unsigned q1 = s_q; unsigned acc1 = s_acc;
    __syncthreads();

    // ---- level 2: middle 11 bits among bin q1 ----
    for (int i = tid; i < 2048; i += 256) hh[i] = 0;
    __syncthreads();
    for (int i = tid; i < n; i += 256) {
        unsigned k = g_ckey[i];
        if ((k >> 21) == q1) atomicAdd(&hh[(k >> 10) & 2047], 1u);
    }
    __syncthreads();
    unsigned sum2 = 0;
    for (int j = 0; j < 8; j++) sum2 += hh[tid * 8 + j];
    csum[tid] = sum2;
    __syncthreads();
    if (tid == 0) {
        unsigned acc = acc1; int chunk = 0;
        for (int c = 255; c >= 0; c--) {
            if (acc + csum[c] >= TOPN) { chunk = c; break; }
            acc += csum[c];
        }
        int bin = chunk * 8;
        for (int j = 7; j >= 0; j--) {
            unsigned h = hh[chunk * 8 + j];
            if (acc + h >= TOPN) { bin = chunk * 8 + j; break; }
            acc += h;
        }
        s_q = (unsigned)bin; s_acc = acc;
    }
    __syncthreads();
    unsigned q2 = s_q; unsigned acc2 = s_acc;
    __syncthreads();

    // ---- level 3: low 10 bits among prefix (q1,q2) ----
    unsigned pref = (q1 << 11) | q2;
    for (int i = tid; i < 1024; i += 256) hh[i] = 0;
    __syncthreads();
    for (int i = tid; i < n; i += 256) {
        unsigned k = g_ckey[i];
        if ((k >> 10) == pref) atomicAdd(&hh[k & 1023], 1u);
    }
    __syncthreads();
    unsigned sum3 = 0;
    for (int j = 0; j < 4; j++) sum3 += hh[tid * 4 + j];
    csum[tid] = sum3;
    __syncthreads();
    if (tid == 0) {
        unsigned acc = acc2; int chunk = 0;
        for (int c = 255; c >= 0; c--) {
            if (acc + csum[c] >= TOPN) { chunk = c; break; }
            acc += csum[c];
        }
        int bin = chunk * 4;
        for (int j = 3; j >= 0; j--) {
            unsigned h = hh[chunk * 4 + j];
            if (acc + h >= TOPN) { bin = chunk * 4 + j; break; }
            acc += h;
        }
        s_q = (unsigned)bin; s_acc = acc;
    }
    __syncthreads();
    unsigned q3 = s_q; unsigned count_gt = s_acc;   // = #keys strictly > thresh
    unsigned thresh = (q1 << 21) | (q2 << 10) | q3;

    // ---- mark > thresh; gather == thresh ----
    if (tid == 0) s_eqn = 0;
    __syncthreads();
    for (int i = tid; i < n; i += 256) {
        unsigned k = g_ckey[i];
        if (k > thresh) {
            int idx = g_cidx[i];
            atomicOr(&g_hi[idx >> 6], 1ull << (idx & 63));
        } else if (k == thresh) {
            unsigned e = atomicAdd(&s_eqn, 1u);
            if (e < EQCAP) s_eq[e] = g_cidx[i];
        }
    }
    __syncthreads();
    if (tid == 0) {
        int need = TOPN - (int)count_gt;
        int m = (int)s_eqn; if (m > EQCAP) m = EQCAP;
        if (need > 0) {
            if (m <= need) {
                for (int j = 0; j < m; j++) {
                    int i = s_eq[j];
                    atomicOr(&g_hi[i >> 6], 1ull << (i & 63));
                }
            } else {
                for (int r = 0; r < need; r++) {
                    int best = 0x7fffffff, bj = -1;
                    for (int j = 0; j < m; j++) {
                        int vv = s_eq[j];
                        if (vv < best) { best = vv; bj = j; }
                    }
                    s_eq[bj] = 0x7fffffff;
                    atomicOr(&g_hi[best >> 6], 1ull << (best & 63));
                }
            }
        }
    }
}

// ---------------- K5: fused W+H dilation for BOTH masks --------------------
__global__ void k_dilwh() {
    int which = blockIdx.x >> 8;            // 0 = pos, 1 = hi
    int bd = blockIdx.x & 255;
    const u64* in = which ? g_hi : g_pos;
    __shared__ u64 sh[128][2];
    int h = threadIdx.x;
    u64 lo = in[(bd * 128 + h) * 2];
    u64 hi = in[(bd * 128 + h) * 2 + 1];
    u64 olo = lo, ohi = hi;
#pragma unroll
    for (int s = 1; s <= 10; s++) {
        olo |= lo << s;
        ohi |= (hi << s) | (lo >> (64 - s));
        olo |= (lo >> s) | (hi << (64 - s));
        ohi |= hi >> s;
    }
    sh[h][0] = olo; sh[h][1] = ohi;
    __syncthreads();
    int h0 = max(h - 10, 0), h1 = min(h + 10, 127);
    u64 rlo = 0, rhi = 0;
    for (int h2 = h0; h2 <= h1; h2++) { rlo |= sh[h2][0]; rhi |= sh[h2][1]; }
    g_tmpA[which * NWORDS + (bd * 128 + h) * 2] = rlo;
    g_tmpA[which * NWORDS + (bd * 128 + h) * 2 + 1] = rhi;
}

// ---------------- K6: D-axis dilation for BOTH masks -----------------------
__global__ void k_dild() {
    int idx = blockIdx.x * blockDim.x + threadIdx.x;     // 0 .. 2*NWORDS-1
    if (idx >= 2 * NWORDS) return;
    int which = idx >> 16;                                // NWORDS = 65536
    int w = idx & (NWORDS - 1);
    int k = w & 1; int h = (w >> 1) & 127; int d = (w >> 8) & 127; int b = w >> 15;
    int d0 = max(d - 10, 0), d1 = min(d + 10, 127);
    const u64* base = g_tmpA + which * NWORDS;
    u64 o = 0;
    for (int d2 = d0; d2 <= d1; d2++) o |= base[((b * 128 + d2) * 128 + h) * 2 + k];
    u64* out = which ? g_hidil : g_posdil;
    out[w] = o;
}

// ---------------- K7: masked sums + last-block finalize --------------------
__global__ __launch_bounds__(256) void k_maskred(float* out) {
    float esum = 0, ecnt = 0, fsum = 0, fcnt = 0;
    int nt = gridDim.x * blockDim.x;
    for (int g = blockIdx.x * blockDim.x + threadIdx.x; g < NV4; g += nt) {
        int i0 = g << 2;
        int w = i0 >> 6; int shamt = i0 & 63;
        u64 pw = g_pos[w] >> shamt;
        u64 pd = g_posdil[w] >> shamt;
        u64 hd = g_hidil[w] >> shamt;
        unsigned any = (unsigned)((pd | hd) & ~pw) & 0xFu;
        if (!any) continue;
        float4 c = *(const float4*)(g_cos + i0);
        float cj[4] = {c.x, c.y, c.z, c.w};
#pragma unroll
        for (int j = 0; j < 4; j++) {
            if (!((pw >> j) & 1ull)) {
                float rc = fmaxf(cj[j], 0.0f);
                if ((pd >> j) & 1ull) { esum += rc; ecnt += 1.0f; }
                if ((hd >> j) & 1ull) { fsum += rc; fcnt += 1.0f; }
            }
        }
    }
    float vals[4] = {esum, ecnt, fsum, fcnt};
    block_accumulate<4>(vals, 27);
    __threadfence();
    __syncthreads();
    if (threadIdx.x == 0) {
        unsigned t = atomicAdd(&g_done, 1u);
        if (t == gridDim.x - 1) {
            g_done = 0u;
            double ce = -(double)g_redf[0] / (double)NV;
            double dcl = 0.0;
            for (int c = 1; c < 3; c++) {
                double tp = g_redf[4 + c];
                double fp = (double)g_redf[1 + c] - tp;
                double fn = (double)g_redf[7 + c] - tp;
                dcl += (2.0 * tp + 1e-5) / fmax(2.0 * tp + fp + fn + 1e-5, 1e-8);
            }
            double dc_loss = -dcl * 0.5;
            double cnt1 = g_redf[8];
            double pos_loss = (cnt1 > 0.0) ? (cnt1 - (double)g_redf[10]) / cnt1 : 0.0;
            double mis_loss = (g_redf[28] > 0.0f) ? (double)g_redf[27] / (double)g_redf[28] : 0.0;
            double neg_loss = (g_redf[30] > 0.0f) ? (double)g_redf[29] / (double)g_redf[30] : 0.0;
            out[0] = (float)(ce + dc_loss + 5.0 * (pos_loss + mis_loss + neg_loss));
        }
    }
}

// ---------------- launch ----------------
extern "C" void kernel_launch(void* const* d_in, const int* in_sizes, int n_in,
                              void* d_out, int out_size) {
    const float* feat = (const float*)d_in[0];
    const float* net  = (const float*)d_in[1];
    const int*   tgt  = (const int*)d_in[2];
    float* out = (float*)d_out;

    k_zero<<<256, 256>>>();
    k_main<<<2048, 256>>>(net, feat, tgt);
    k_cos<<<2048, 256>>>(feat, tgt);
    k_collect<<<1024, 256>>>();
    k_topk<<<1, 256>>>();
    k_dilwh<<<512, 128>>>();
    k_dild<<<512, 256>>>();
    k_maskred<<<1024, 256>>>(out);
}

// round 17
// speedup vs baseline: 2.5861x; 1.0464x over previous
#include <cuda_runtime.h>
#include <math.h>

// Shapes: feature (2,16,128,128,128) f32, net_output (2,3,128,128,128) f32,
// target (2,1,128,128,128) i32. Output: scalar f32.
#define VV   (128*128*128)      /* 2^21 voxels per batch */
#define NV   (2*VV)             /* 4,194,304 */
#define NV4  (NV/4)
#define NWORDS (NV/64)          /* 65536 bitset words */
#define TOPN 250
#define CCAP 65536
#define EQCAP 2048
#define STATIC_T 0.70f          /* static candidate threshold (see k_fallback guard) */

typedef unsigned long long u64;

// ---------------- device scratch ----------------
// g_redf layout: 0 ce_sum | 1..3 sum_p[c] | 4..6 tp[c] | 7..9 cnt[c]
//                10 pos_cos_sum | 11..26 featsum[16]
//                27 easy_sum | 28 easy_cnt | 29 fneg_sum | 30 fneg_cnt
__device__ float g_redf[32];
__device__ unsigned g_histA[2048];
__device__ unsigned g_ccnt, g_done;
__device__ unsigned g_ckey[CCAP];
__device__ int g_cidx[CCAP];
__device__ float g_cos[NV];
__device__ u64 g_pos[NWORDS];
__device__ u64 g_neg[NWORDS];
__device__ u64 g_hi[NWORDS];
__device__ u64 g_tmpA[2 * NWORDS];
__device__ u64 g_posdil[NWORDS];
__device__ u64 g_hidil[NWORDS];

// ---------------- helpers ----------------
__device__ __forceinline__ unsigned fmono(float f) {
    unsigned u = __float_as_uint(f);
    return (u & 0x80000000u) ? ~u : (u | 0x80000000u);
}

__device__ __forceinline__ float warp_sumf(float v) {
#pragma unroll
    for (int o = 16; o; o >>= 1) v += __shfl_down_sync(0xffffffffu, v, o);
    return v;
}

template<int N>
__device__ __forceinline__ void block_accumulate(const float* vals, int base) {
    __shared__ float sh[N];
    if (threadIdx.x < N) sh[threadIdx.x] = 0.0f;
    __syncthreads();
    int lane = threadIdx.x & 31;
#pragma unroll
    for (int k = 0; k < N; k++) {
        float w = warp_sumf(vals[k]);
        if (lane == 0 && w != 0.0f) atomicAdd(&sh[k], w);
    }
    __syncthreads();
    if (threadIdx.x < N && sh[threadIdx.x] != 0.0f)
        atomicAdd(&g_redf[base + threadIdx.x], sh[threadIdx.x]);
}

// ---------------- K0: zero scratch ----------------
__global__ void k_zero() {
    int i = blockIdx.x * blockDim.x + threadIdx.x;
    if (i < 2048) g_histA[i] = 0;
    if (i < NWORDS) { g_pos[i] = 0ull; g_neg[i] = 0ull; g_hi[i] = 0ull; }
    if (i < 32) g_redf[i] = 0.0f;
    if (i == 0) { g_ccnt = 0u; g_done = 0u; }
}

// ---------------- K1: CE + Dice stats + per-channel positive feature sums --
__global__ __launch_bounds__(256) void k_main(const float* __restrict__ net,
                                              const float* __restrict__ feat,
                                              const int* __restrict__ tgt) {
    float ce = 0, sp0 = 0, sp1 = 0, sp2 = 0;
    float tp0 = 0, tp1 = 0, tp2 = 0, c0 = 0, c1 = 0, c2 = 0;
    float s[16];
#pragma unroll
    for (int c = 0; c < 16; c++) s[c] = 0.0f;
    int nt = gridDim.x * blockDim.x;
    for (int g = blockIdx.x * blockDim.x + threadIdx.x; g < NV4; g += nt) {
        int i0 = g << 2;
        int b = i0 >> 21; int v = i0 & (VV - 1);
        int4 tt = *(const int4*)(tgt + i0);
        // --- CE/Dice part ---
        const float* base = net + (size_t)b * 3 * VV + v;
        float4 x0 = *(const float4*)(base);
        float4 x1 = *(const float4*)(base + VV);
        float4 x2 = *(const float4*)(base + 2 * (size_t)VV);
        float a0[4] = {x0.x, x0.y, x0.z, x0.w};
        float a1[4] = {x1.x, x1.y, x1.z, x1.w};
        float a2[4] = {x2.x, x2.y, x2.z, x2.w};
        int ts[4] = {tt.x, tt.y, tt.z, tt.w};
#pragma unroll
        for (int j = 0; j < 4; j++) {
            float xa = a0[j], xb = a1[j], xc = a2[j];
            float m = fmaxf(xa, fmaxf(xb, xc));
            float e0 = __expf(xa - m), e1 = __expf(xb - m), e2 = __expf(xc - m);
            float ssum = e0 + e1 + e2;
            float ls = __logf(ssum);
            int t = ts[j];
            float xt = (t == 0) ? xa : ((t == 1) ? xb : xc);
            ce += xt - m - ls;
            float inv = __frcp_rn(ssum);
            float p0 = e0 * inv, p1 = e1 * inv, p2 = e2 * inv;
            sp0 += p0; sp1 += p1; sp2 += p2;
            float pt = (t == 0) ? p0 : ((t == 1) ? p1 : p2);
            tp0 += (t == 0) ? pt : 0.0f;  c0 += (t == 0) ? 1.0f : 0.0f;
            tp1 += (t == 1) ? pt : 0.0f;  c1 += (t == 1) ? 1.0f : 0.0f;
            tp2 += (t == 2) ? pt : 0.0f;  c2 += (t == 2) ? 1.0f : 0.0f;
        }
        // --- featsum part ---
        float m0 = (tt.x == 1) ? 1.0f : 0.0f;
        float m1 = (tt.y == 1) ? 1.0f : 0.0f;
        float m2 = (tt.z == 1) ? 1.0f : 0.0f;
        float m3 = (tt.w == 1) ? 1.0f : 0.0f;
        const float* fb = feat + (size_t)b * 16 * VV + v;
#pragma unroll
        for (int c = 0; c < 16; c++) {
            float4 x = *(const float4*)(fb + (size_t)c * VV);
            s[c] += x.x * m0 + x.y * m1 + x.z * m2 + x.w * m3;
        }
    }
    float acc[10] = {ce, sp0, sp1, sp2, tp0, tp1, tp2, c0, c1, c2};
    block_accumulate<10>(acc, 0);
    block_accumulate<16>(s, 11);
}

// ---------------- K2: cos map + bitsets + pos sum + hist + static collect --
// std_n computed inline: sum/||sum|| == mean/||mean|| (count cancels).
// Candidates (neg, cos > STATIC_T) are collected inline; k_fallback guards
// the (improbable) case that fewer than TOPN such candidates exist.
__global__ __launch_bounds__(256) void k_cos(const float* __restrict__ feat,
                                             const int* __restrict__ tgt) {
    __shared__ unsigned hh[2048];
    __shared__ float s_sum[16];
    for (int i = threadIdx.x; i < 2048; i += blockDim.x) hh[i] = 0;
    if (threadIdx.x < 16) s_sum[threadIdx.x] = g_redf[11 + threadIdx.x];
    __syncthreads();
    float nrm2 = 0.0f;
#pragma unroll
    for (int c = 0; c < 16; c++) nrm2 += s_sum[c] * s_sum[c];
    float nrm = sqrtf(nrm2);
    float rinv = (nrm > 1e-30f) ? __frcp_rn(nrm) : 0.0f;
    float sn[16];
#pragma unroll
    for (int c = 0; c < 16; c++) sn[c] = s_sum[c] * rinv;

    float psum = 0.0f;
    int nt = gridDim.x * blockDim.x;
    for (int g = blockIdx.x * blockDim.x + threadIdx.x; g < NV4; g += nt) {
        int i0 = g << 2;
        int b = i0 >> 21; int v = i0 & (VV - 1);
        const float* fb = feat + (size_t)b * 16 * VV + v;
        float d0 = 0, d1 = 0, d2 = 0, d3 = 0;
        float n0 = 0, n1 = 0, n2 = 0, n3 = 0;
#pragma unroll
        for (int c = 0; c < 16; c++) {
            float4 x = *(const float4*)(fb + (size_t)c * VV);
            d0 += x.x * sn[c]; n0 += x.x * x.x;
            d1 += x.y * sn[c]; n1 += x.y * x.y;
            d2 += x.z * sn[c]; n2 += x.z * x.z;
            d3 += x.w * sn[c]; n3 += x.w * x.w;
        }
        float4 cs;
        cs.x = d0 / fmaxf(sqrtf(n0), 1e-12f);
        cs.y = d1 / fmaxf(sqrtf(n1), 1e-12f);
        cs.z = d2 / fmaxf(sqrtf(n2), 1e-12f);
        cs.w = d3 / fmaxf(sqrtf(n3), 1e-12f);
        *(float4*)(g_cos + i0) = cs;
        int4 tt = *(const int4*)(tgt + i0);
        float cj[4] = {cs.x, cs.y, cs.z, cs.w};
        int ts[4] = {tt.x, tt.y, tt.z, tt.w};
        unsigned posbits = 0, negbits = 0;
#pragma unroll
        for (int j = 0; j < 4; j++) {
            if (ts[j] == 1) { psum += cj[j]; posbits |= (1u << j); }
            else if (ts[j] == 0) {
                negbits |= (1u << j);
                unsigned k = fmono(cj[j]);
                atomicAdd(&hh[k >> 21], 1u);
                if (cj[j] > STATIC_T) {
                    unsigned id = atomicAdd(&g_ccnt, 1u);
                    if (id < CCAP) { g_ckey[id] = k; g_cidx[id] = i0 + j; }
                }
            }
        }
        if (posbits) atomicOr(&g_pos[i0 >> 6], ((u64)posbits) << (i0 & 63));
        if (negbits) atomicOr(&g_neg[i0 >> 6], ((u64)negbits) << (i0 & 63));
    }
    __syncthreads();
    for (int i = threadIdx.x; i < 2048; i += blockDim.x) {
        unsigned hv = hh[i];
        if (hv) atomicAdd(&g_histA[i], hv);
    }
    float one[1] = {psum};
    block_accumulate<1>(one, 10);
}

// ---------------- K3: fallback collect (only if static set too small) ------
// Collects keys in [p1_bin_start, fmono(STATIC_T)) — disjoint from the static
// set, so the union is exactly {keys >= p1_bin_start}: a top-250 superset.
__global__ __launch_bounds__(256) void k_fallback() {
    if (g_ccnt >= TOPN) return;            // common path: static set suffices
    __shared__ unsigned sh[2048];
    __shared__ unsigned csum[256];
    __shared__ unsigned s_p1;
    int tid = threadIdx.x;
    for (int i = tid; i < 2048; i += 256) sh[i] = g_histA[i];
    __syncthreads();
    unsigned s = 0;
    for (int j = 0; j < 8; j++) s += sh[tid * 8 + j];
    csum[tid] = s;
    __syncthreads();
    if (tid == 0) {
        unsigned acc = 0; int chunk = 0;
        for (int c = 255; c >= 0; c--) {
            if (acc + csum[c] >= TOPN) { chunk = c; break; }
            acc += csum[c];
        }
        int bin = chunk * 8;
        for (int j = 7; j >= 0; j--) {
            unsigned h = sh[chunk * 8 + j];
            if (acc + h >= TOPN) { bin = chunk * 8 + j; break; }
            acc += h;
        }
        s_p1 = (unsigned)bin;
    }
    __syncthreads();
    unsigned p1 = s_p1;
    unsigned t_s = fmono(STATIC_T);
    int nt = gridDim.x * blockDim.x;
    for (int g = blockIdx.x * blockDim.x + tid; g < NV4; g += nt) {
        int i0 = g << 2;
        unsigned nb = (unsigned)(g_neg[i0 >> 6] >> (i0 & 63)) & 0xFu;
        if (!nb) continue;
        float4 c = *(const float4*)(g_cos + i0);
        float cj[4] = {c.x, c.y, c.z, c.w};
#pragma unroll
        for (int j = 0; j < 4; j++) {
            if ((nb >> j) & 1u) {
                unsigned k = fmono(cj[j]);
                if ((k >> 21) >= p1 && k < t_s) {
                    unsigned id = atomicAdd(&g_ccnt, 1u);
                    if (id < CCAP) { g_ckey[id] = k; g_cidx[id] = i0 + j; }
                }
            }
        }
    }
}

// ---------------- K4: single-block top-250 among candidates ----------------
__global__ __launch_bounds__(256) void k_topk() {
    __shared__ unsigned hh[2048];
    __shared__ unsigned csum[256];
    __shared__ unsigned s_q, s_acc;
    __shared__ int s_eq[EQCAP];
    __shared__ unsigned s_eqn;
    int tid = threadIdx.x;
    int n = (int)min(g_ccnt, (unsigned)CCAP);

    // ---- level 1: top 11 bits ----
    for (int i = tid; i < 2048; i += 256) hh[i] = 0;
    __syncthreads();
    for (int i = tid; i < n; i += 256) atomicAdd(&hh[g_ckey[i] >> 21], 1u);
    __syncthreads();
    unsigned sum1 = 0;
    for (int j = 0; j < 8; j++) sum1 += hh[tid * 8 + j];
    csum[tid] = sum1;
    __syncthreads();
    if (tid == 0) {
        unsigned acc = 0; int chunk = 0;
        for (int c = 255; c >= 0; c--) {
            if (acc + csum[c] >= TOPN) { chunk = c; break; }
            acc += csum[c];
        }
        int bin = chunk * 8;
        for (int j = 7; j >= 0; j--) {
            unsigned h = hh[chunk * 8 + j];
            if (acc + h >= TOPN) { bin = chunk * 8 + j; break; }
            acc += h;
        }
        s_q = (unsigned)bin; s_acc = acc;
    }
    __syncthreads();
    unsigned q1 = s_q; unsigned acc1 = s_acc;
    __syncthreads();

    // ---- level 2: middle 11 bits among bin q1 ----
    for (int i = tid; i < 2048; i += 256) hh[i] = 0;
    __syncthreads();
    for (int i = tid; i < n; i += 256) {
        unsigned k = g_ckey[i];
        if ((k >> 21) == q1) atomicAdd(&hh[(k >> 10) & 2047], 1u);
    }
    __syncthreads();
    unsigned sum2 = 0;
    for (int j = 0; j < 8; j++) sum2 += hh[tid * 8 + j];
    csum[tid] = sum2;
    __syncthreads();
    if (tid == 0) {
        unsigned acc = acc1; int chunk = 0;
        for (int c = 255; c >= 0; c--) {
            if (acc + csum[c] >= TOPN) { chunk = c; break; }
            acc += csum[c];
        }
        int bin = chunk * 8;
        for (int j = 7; j >= 0; j--) {
            unsigned h = hh[chunk * 8 + j];
            if (acc + h >= TOPN) { bin = chunk * 8 + j; break; }
            acc += h;
        }
        s_q = (unsigned)bin; s_acc = acc;
    }
    __syncthreads();
    unsigned q2 = s_q; unsigned acc2 = s_acc;
    __syncthreads();

    // ---- level 3: low 10 bits among prefix (q1,q2) ----
    unsigned pref = (q1 << 11) | q2;
    for (int i = tid; i < 1024; i += 256) hh[i] = 0;
    __syncthreads();
    for (int i = tid; i < n; i += 256) {
        unsigned k = g_ckey[i];
        if ((k >> 10) == pref) atomicAdd(&hh[k & 1023], 1u);
    }
    __syncthreads();
    unsigned sum3 = 0;
    for (int j = 0; j < 4; j++) sum3 += hh[tid * 4 + j];
    csum[tid] = sum3;
    __syncthreads();
    if (tid == 0) {
        unsigned acc = acc2; int chunk = 0;
        for (int c = 255; c >= 0; c--) {
            if (acc + csum[c] >= TOPN) { chunk = c; break; }
            acc += csum[c];
        }
        int bin = chunk * 4;
        for (int j = 3; j >= 0; j--) {
            unsigned h = hh[chunk * 4 + j];
            if (acc + h >= TOPN) { bin = chunk * 4 + j; break; }
            acc += h;
        }
        s_q = (unsigned)bin; s_acc = acc;
    }
    __syncthreads();
    unsigned q3 = s_q; unsigned count_gt = s_acc;   // = #keys strictly > thresh
    unsigned thresh = (q1 << 21) | (q2 << 10) | q3;

    // ---- mark > thresh; gather == thresh ----
    if (tid == 0) s_eqn = 0;
    __syncthreads();
    for (int i = tid; i < n; i += 256) {
        unsigned k = g_ckey[i];
        if (k > thresh) {
            int idx = g_cidx[i];
            atomicOr(&g_hi[idx >> 6], 1ull << (idx & 63));
        } else if (k == thresh) {
            unsigned e = atomicAdd(&s_eqn, 1u);
            if (e < EQCAP) s_eq[e] = g_cidx[i];
        }
    }
    __syncthreads();
    if (tid == 0) {
        int need = TOPN - (int)count_gt;
        int m = (int)s_eqn; if (m > EQCAP) m = EQCAP;
        if (need > 0) {
            if (m <= need) {
                for (int j = 0; j < m; j++) {
                    int i = s_eq[j];
                    atomicOr(&g_hi[i >> 6], 1ull << (i & 63));
                }
            } else {
                for (int r = 0; r < need; r++) {
                    int best = 0x7fffffff, bj = -1;
                    for (int j = 0; j < m; j++) {
                        int vv = s_eq[j];
                        if (vv < best) { best = vv; bj = j; }
                    }
                    s_eq[bj] = 0x7fffffff;
                    atomicOr(&g_hi[best >> 6], 1ull << (best & 63));
                }
            }
        }
    }
}

// ---------------- K5: fused W+H dilation for BOTH masks --------------------
__global__ void k_dilwh() {
    int which = blockIdx.x >> 8;            // 0 = pos, 1 = hi
    int bd = blockIdx.x & 255;
    const u64* in = which ? g_hi : g_pos;
    __shared__ u64 sh[128][2];
    int h = threadIdx.x;
    u64 lo = in[(bd * 128 + h) * 2];
    u64 hi = in[(bd * 128 + h) * 2 + 1];
    u64 olo = lo, ohi = hi;
#pragma unroll
    for (int s = 1; s <= 10; s++) {
        olo |= lo << s;
        ohi |= (hi << s) | (lo >> (64 - s));
        olo |= (lo >> s) | (hi << (64 - s));
        ohi |= hi >> s;
    }
    sh[h][0] = olo; sh[h][1] = ohi;
    __syncthreads();
    int h0 = max(h - 10, 0), h1 = min(h + 10, 127);
    u64 rlo = 0, rhi = 0;
    for (int h2 = h0; h2 <= h1; h2++) { rlo |= sh[h2][0]; rhi |= sh[h2][1]; }
    g_tmpA[which * NWORDS + (bd * 128 + h) * 2] = rlo;
    g_tmpA[which * NWORDS + (bd * 128 + h) * 2 + 1] = rhi;
}

// ---------------- K6: D-axis dilation for BOTH masks -----------------------
__global__ void k_dild() {
    int idx = blockIdx.x * blockDim.x + threadIdx.x;     // 0 .. 2*NWORDS-1
    if (idx >= 2 * NWORDS) return;
    int which = idx >> 16;                                // NWORDS = 65536
    int w = idx & (NWORDS - 1);
    int k = w & 1; int h = (w >> 1) & 127; int d = (w >> 8) & 127; int b = w >> 15;
    int d0 = max(d - 10, 0), d1 = min(d + 10, 127);
    const u64* base = g_tmpA + which * NWORDS;
    u64 o = 0;
    for (int d2 = d0; d2 <= d1; d2++) o |= base[((b * 128 + d2) * 128 + h) * 2 + k];
    u64* out = which ? g_hidil : g_posdil;
    out[w] = o;
}

// ---------------- K7: masked sums (unconditional stream) + finalize --------
__global__ __launch_bounds__(256) void k_maskred(float* out) {
    float esum = 0, ecnt = 0, fsum = 0, fcnt = 0;
    int nt = gridDim.x * blockDim.x;
    for (int g = blockIdx.x * blockDim.x + threadIdx.x; g < NV4; g += nt) {
        int i0 = g << 2;
        int w = i0 >> 6; int shamt = i0 & 63;
        u64 pw = g_pos[w] >> shamt;
        u64 pd = g_posdil[w] >> shamt;
        u64 hd = g_hidil[w] >> shamt;
        float4 c = *(const float4*)(g_cos + i0);     // unconditional: keep MLP high
        float cj[4] = {c.x, c.y, c.z, c.w};
#pragma unroll
        for (int j = 0; j < 4; j++) {
            if (!((pw >> j) & 1ull)) {
                float rc = fmaxf(cj[j], 0.0f);
                if ((pd >> j) & 1ull) { esum += rc; ecnt += 1.0f; }
                if ((hd >> j) & 1ull) { fsum += rc; fcnt += 1.0f; }
            }
        }
    }
    float vals[4] = {esum, ecnt, fsum, fcnt};
    block_accumulate<4>(vals, 27);
    __threadfence();
    __syncthreads();
    if (threadIdx.x == 0) {
        unsigned t = atomicAdd(&g_done, 1u);
        if (t == gridDim.x - 1) {
            g_done = 0u;
            double ce = -(double)g_redf[0] / (double)NV;
            double dcl = 0.0;
            for (int c = 1; c < 3; c++) {
                double tp = g_redf[4 + c];
                double fp = (double)g_redf[1 + c] - tp;
                double fn = (double)g_redf[7 + c] - tp;
                dcl += (2.0 * tp + 1e-5) / fmax(2.0 * tp + fp + fn + 1e-5, 1e-8);
            }
            double dc_loss = -dcl * 0.5;
            double cnt1 = g_redf[8];
            double pos_loss = (cnt1 > 0.0) ? (cnt1 - (double)g_redf[10]) / cnt1 : 0.0;
            double mis_loss = (g_redf[28] > 0.0f) ? (double)g_redf[27] / (double)g_redf[28] : 0.0;
            double neg_loss = (g_redf[30] > 0.0f) ? (double)g_redf[29] / (double)g_redf[30] : 0.0;
            out[0] = (float)(ce + dc_loss + 5.0 * (pos_loss + mis_loss + neg_loss));
        }
    }
}

// ---------------- launch ----------------
extern "C" void kernel_launch(void* const* d_in, const int* in_sizes, int n_in,
                              void* d_out, int out_size) {
    const float* feat = (const float*)d_in[0];
    const float* net  = (const float*)d_in[1];
    const int*   tgt  = (const int*)d_in[2];
    float* out = (float*)d_out;

    k_zero<<<256, 256>>>();
    k_main<<<2048, 256>>>(net, feat, tgt);
    k_cos<<<2048, 256>>>(feat, tgt);
    k_fallback<<<1024, 256>>>();
    k_topk<<<1, 256>>>();
    k_dilwh<<<512, 128>>>();
    k_dild<<<512, 256>>>();
    k_maskred<<<1024, 256>>>(out);
}